// round 14
// baseline (speedup 1.0000x reference)
#include <cuda_runtime.h>

// ---------------------------------------------------------------------------
// GroupedQueryAttention — single fused persistent kernel (R12 base).
//   x_embed affine in scalar x[b,s] => score(log2) = a[g,p]*x[b,s] + bconst[g,p,s]
//   attn = e/Z ; ctx = invZ*(sum_s e*vc[s,:] + (sum_s e*x)*vw) ; out = ctx@o_w+o_b
//
// Grid (74,2) = 148 CTAs = 1/SM -> co-resident; ticket barriers safe.
// Phase 1: distributed table build (7 s-rows per CTA), ticket barrier.
// Phase 2: main loop, FAT-ITER variant: 8 iterations per chunk, each lane owns
//   4 consecutive s (two s2-pairs) -> attn stores are STG.128 and x loads are
//   LDS.128 (fewer issue slots, identical bytes/EX2/FMA vs measured-best R12).
// Phase 3: ticket barrier, fused out-projection (7 b-rows per CTA).
// ---------------------------------------------------------------------------

#define LOG2E_OVER_SCALE ((float)(1.4426950408889634 / 2.8284271247461903))

// g_b4[g][wp][s2][4] = { b(2s2,p0), b(2s2,p1), b(2s2+1,p0), b(2s2+1,p1) }
__device__ __align__(16) float g_b4[2][16][512][4];   // 256 KB
// g_vc4[g][jj][s2][4] = { vc(2s2,2jj), vc(2s2,2jj+1), vc(2s2+1,2jj), vc(2s2+1,2jj+1) }
__device__ __align__(16) float g_vc4[2][4][512][4];   // 64 KB
__device__ float g_a[2][32];
__device__ float g_vw[2][8];
__device__ __align__(16) float g_ctxs[1024][8][64];   // 2 MB staging
__device__ unsigned g_done1;
__device__ unsigned g_done2;

__device__ __forceinline__ float ex2f(float x) {
    float r; asm("ex2.approx.ftz.f32 %0, %1;" : "=f"(r) : "f"(x)); return r;
}
__device__ __forceinline__ unsigned long long pack2(float a, float b) {
    unsigned long long r; asm("mov.b64 %0, {%1, %2};" : "=l"(r) : "f"(a), "f"(b)); return r;
}
__device__ __forceinline__ void unpack2(unsigned long long v, float& a, float& b) {
    asm("mov.b64 {%0, %1}, %2;" : "=f"(a), "=f"(b) : "l"(v));
}
__device__ __forceinline__ void fma2(unsigned long long& d, unsigned long long a, unsigned long long b) {
    asm("fma.rn.f32x2 %0, %1, %2, %0;" : "+l"(d) : "l"(a), "l"(b));
}
__device__ __forceinline__ float wsum(float v) {
#pragma unroll
    for (int m = 16; m > 0; m >>= 1) v += __shfl_xor_sync(0xffffffffu, v, m);
    return v;
}
__device__ __forceinline__ void ticket_barrier(unsigned* ctr, int tid) {
    __threadfence();
    __syncthreads();
    if (tid == 0) {
        unsigned ticket = atomicAdd(ctr, 1u);
        unsigned target = ticket - (ticket % 148u) + 148u;
        while ((int)(atomicAdd(ctr, 0u) - target) < 0) __nanosleep(128);
    }
    __syncthreads();
    __threadfence();
}

__global__ __launch_bounds__(512, 1) void k_fused(
        const float* __restrict__ x,
        const float* __restrict__ queries,
        const float* __restrict__ fe_w,
        const float* __restrict__ fe_b,
        const float* __restrict__ pos_emb,
        const float* __restrict__ k_w,
        const float* __restrict__ k_b,
        const float* __restrict__ v_w,
        const float* __restrict__ v_b,
        const float* __restrict__ o_w,
        const float* __restrict__ o_b,
        float* __restrict__ out,
        float* __restrict__ attn_out) {
    extern __shared__ float smem[];
    // main-phase regions:
    float4* sm_vc = (float4*)smem;                  // [4][512] f4  = 32 KB
    float2* sm_x = (float2*)(smem + 8192);          // [2 buf][2 rows][512] f2 = 16 KB
    // prologue scratch (overlays sm_vc region; dead after barrier 1):
    float* s_kw = smem;                             // [64][16] = 1024 f
    float* s_vw = smem + 1024;                      // 1024 f
    float* s_q = smem + 2048;                       // 512 f
    float* s_feb = smem + 2560;                     // 64 f
    float* s_red = smem + 2624;                     // [2][2][16][8] = 512 f
    float* s_kcrow = smem + 3136;                   // [2][16] = 32 f

    const int tid = threadIdx.x;
    const int g = blockIdx.y;
    const int cid = blockIdx.y * 74 + blockIdx.x;   // 0..147

    // ================= PHASE 1: distributed table build =================
    if (tid < 256) ((float4*)s_kw)[tid] = ((const float4*)k_w)[tid];
    else ((float4*)s_vw)[tid - 256] = ((const float4*)v_w)[tid - 256];
    if (tid < 128) ((float4*)s_q)[tid] = ((const float4*)queries)[tid];
    else if (tid < 144) ((float4*)s_feb)[tid - 128] = ((const float4*)fe_b)[tid - 128];
    __syncthreads();

    {
        const int rr = tid >> 8;              // 0/1: two s-rows per pass
        const int tt = tid & 255;
        const int j = tt & 15, d8 = (tt >> 4) & 7, kv = tt >> 7;
        for (int ro = 0; ro < 4; ro++) {
            const int r = 2 * ro + rr;
            const int s = cid + 148 * r;
            const bool valid = (r < 7) && (s < 1024);
            float part = 0.f;
            if (valid) {
                const float* pos = pos_emb + s * 64;
                const float* wcol = kv ? s_vw : s_kw;
#pragma unroll
                for (int u = 0; u < 8; u++) {
                    int d = d8 * 8 + u;
                    float e = s_feb[d] + __ldg(&pos[d]);
                    part = fmaf(e, wcol[d * 16 + j], part);
                }
            }
            s_red[((rr * 2 + kv) * 16 + j) * 8 + d8] = part;
            __syncthreads();
            if (tid < 64) {   // combine 8 d-partials; write vc, hold kc
                int rr2 = tid >> 5, kv2 = (tid >> 4) & 1, j2 = tid & 15;
                const float* pr = &s_red[((rr2 * 2 + kv2) * 16 + j2) * 8];
                float v = pr[0] + pr[1] + pr[2] + pr[3] + pr[4] + pr[5] + pr[6] + pr[7];
                int r2 = 2 * ro + rr2;
                int s2r = cid + 148 * r2;
                if (r2 < 7 && s2r < 1024) {
                    if (kv2 == 0) {
                        s_kcrow[rr2 * 16 + j2] = __ldg(&k_b[j2]) + v;
                    } else {
                        float vc = __ldg(&v_b[j2]) + v;
                        g_vc4[j2 >> 3][(j2 & 7) >> 1][s2r >> 1][(s2r & 1) * 2 + (j2 & 1)] = vc;
                    }
                }
            }
            __syncthreads();
            if (tid < 128) {  // bconst for the two rows
                int rr3 = tid >> 6, pp = tid & 63;
                int gg = pp >> 5, p = pp & 31, rb = p >> 3, q = p & 7, h = gg * 4 + rb;
                int r3 = 2 * ro + rr3;
                int s3 = cid + 148 * r3;
                if (r3 < 7 && s3 < 1024) {
                    float acc = 0.f;
#pragma unroll
                    for (int j3 = 0; j3 < 8; j3++)
                        acc = fmaf(s_q[q * 64 + h * 8 + j3], s_kcrow[rr3 * 16 + gg * 8 + j3], acc);
                    g_b4[gg][p >> 1][s3 >> 1][(s3 & 1) * 2 + (p & 1)] = acc * LOG2E_OVER_SCALE;
                }
            }
            __syncthreads();
        }
    }
    if (cid == 0) {   // a[] and vw (once)
        if (tid < 32) {
            int j = tid & 15, kv = tid >> 4;
            const float* wcol = kv ? s_vw : s_kw;
            float pk = 0.f;
            for (int d = 0; d < 64; d++)
                pk = fmaf(__ldg(&fe_w[d]), wcol[d * 16 + j], pk);
            if (kv) g_vw[j >> 3][j & 7] = pk;
            else s_kcrow[j] = pk;   // reuse as kwf
        }
        __syncthreads();
        if (tid < 64) {
            int gg = tid >> 5, p = tid & 31, rb = p >> 3, q = p & 7, h = gg * 4 + rb;
            float sv = 0.f;
#pragma unroll
            for (int j = 0; j < 8; j++)
                sv = fmaf(s_q[q * 64 + h * 8 + j], s_kcrow[gg * 8 + j], sv);
            g_a[gg][p] = sv * LOG2E_OVER_SCALE;
        }
    }

    ticket_barrier(&g_done1, tid);

    // ================= PHASE 2: main (fat-iter STG.128 variant) ============
    const int w = tid >> 5, lane = tid & 31;
    const int p0 = 2 * w, p1 = p0 + 1;
    const float a0 = g_a[g][p0], a1 = g_a[g][p1];
    const int h0 = g * 4 + (p0 >> 3), q0 = p0 & 7;
    const int h1 = g * 4 + (p1 >> 3), q1 = p1 & 7;

    {
        const float4* vs = (const float4*)&g_vc4[g][0][0][0];
#pragma unroll
        for (int i = 0; i < 4; i++) sm_vc[tid + 512 * i] = vs[tid + 512 * i];
    }

    const int c0 = blockIdx.x;
    const float4* bptr = (const float4*)&g_b4[g][w][0][0];

    // ---- prologue: x + Z for first chunk (thin-iter, mapping-agnostic) ----
    ((float4*)sm_x)[tid] = ((const float4*)(x + (size_t)(2 * c0) * 1024))[tid];
    __syncthreads();
    float izA0, izA1, izB0, izB1;
    {
        float zA0 = 0.f, zA1 = 0.f, zB0 = 0.f, zB1 = 0.f;
#pragma unroll
        for (int i = 0; i < 16; i++) {
            int s2 = 32 * i + lane;
            float4 bb = bptr[s2];
            float2 xA = sm_x[s2];
            float2 xB = sm_x[512 + s2];
            zA0 += ex2f(fmaf(a0, xA.x, bb.x)) + ex2f(fmaf(a0, xA.y, bb.z));
            zA1 += ex2f(fmaf(a1, xA.x, bb.y)) + ex2f(fmaf(a1, xA.y, bb.w));
            zB0 += ex2f(fmaf(a0, xB.x, bb.x)) + ex2f(fmaf(a0, xB.y, bb.z));
            zB1 += ex2f(fmaf(a1, xB.x, bb.y)) + ex2f(fmaf(a1, xB.y, bb.w));
        }
        izA0 = 1.0f / wsum(zA0); izA1 = 1.0f / wsum(zA1);
        izB0 = 1.0f / wsum(zB0); izB1 = 1.0f / wsum(zB1);
    }

    int cur = 0;
    for (int c = c0; c < 512; c += 74) {
        const int b0 = 2 * c, b1 = b0 + 1;
        const int cn = c + 74;
        if (cn < 512)
            ((float4*)&sm_x[(cur ^ 1) * 1024])[tid] =
                ((const float4*)(x + (size_t)(2 * cn) * 1024))[tid];
        __syncthreads();

        const float4* xc4 = (const float4*)&sm_x[cur * 1024];        // [256] per row
        const float4* xn4 = (const float4*)&sm_x[(cur ^ 1) * 1024];
        float4* pA0 = (float4*)(attn_out + (((size_t)b0 * 8 + h0) * 8 + q0) * 1024) + lane;
        float4* pA1 = (float4*)(attn_out + (((size_t)b0 * 8 + h1) * 8 + q1) * 1024) + lane;
        float4* pB0 = (float4*)(attn_out + (((size_t)b1 * 8 + h0) * 8 + q0) * 1024) + lane;
        float4* pB1 = (float4*)(attn_out + (((size_t)b1 * 8 + h1) * 8 + q1) * 1024) + lane;

        float znA0 = 0.f, znA1 = 0.f, znB0 = 0.f, znB1 = 0.f;
        float xsA0 = 0.f, xsA1 = 0.f, xsB0 = 0.f, xsB1 = 0.f;
        unsigned long long cA0[4], cA1[4], cB0[4], cB1[4];
#pragma unroll
        for (int k = 0; k < 4; k++) { cA0[k] = cA1[k] = cB0[k] = cB1[k] = 0ull; }

#pragma unroll
        for (int i = 0; i < 8; i++) {
            const int f4i = 32 * i + lane;       // float4 index: 0..255
            const int S2 = 2 * f4i;              // first s2 pair of this lane
            float4 bb0 = bptr[S2];
            float4 bb1 = bptr[S2 + 1];
            float4 xA = xc4[f4i];
            float4 xB = xc4[256 + f4i];
            float4 nA = xn4[f4i];
            float4 nB = xn4[256 + f4i];

            // ---- Z pipeline for next chunk (16 EX2) ----
            znA0 += ex2f(fmaf(a0, nA.x, bb0.x)) + ex2f(fmaf(a0, nA.y, bb0.z))
                  + ex2f(fmaf(a0, nA.z, bb1.x)) + ex2f(fmaf(a0, nA.w, bb1.z));
            znA1 += ex2f(fmaf(a1, nA.x, bb0.y)) + ex2f(fmaf(a1, nA.y, bb0.w))
                  + ex2f(fmaf(a1, nA.z, bb1.y)) + ex2f(fmaf(a1, nA.w, bb1.w));
            znB0 += ex2f(fmaf(a0, nB.x, bb0.x)) + ex2f(fmaf(a0, nB.y, bb0.z))
                  + ex2f(fmaf(a0, nB.z, bb1.x)) + ex2f(fmaf(a0, nB.w, bb1.z));
            znB1 += ex2f(fmaf(a1, nB.x, bb0.y)) + ex2f(fmaf(a1, nB.y, bb0.w))
                  + ex2f(fmaf(a1, nB.z, bb1.y)) + ex2f(fmaf(a1, nB.w, bb1.w));

            // ---- e values for 4 streams x 4 s (32 EX2 total incl. Z) ----
            float e00 = ex2f(fmaf(a0, xA.x, bb0.x));
            float e01 = ex2f(fmaf(a0, xA.y, bb0.z));
            float e02 = ex2f(fmaf(a0, xA.z, bb1.x));
            float e03 = ex2f(fmaf(a0, xA.w, bb1.z));
            float e10 = ex2f(fmaf(a1, xA.x, bb0.y));
            float e11 = ex2f(fmaf(a1, xA.y, bb0.w));
            float e12 = ex2f(fmaf(a1, xA.z, bb1.y));
            float e13 = ex2f(fmaf(a1, xA.w, bb1.w));
            float f00 = ex2f(fmaf(a0, xB.x, bb0.x));
            float f01 = ex2f(fmaf(a0, xB.y, bb0.z));
            float f02 = ex2f(fmaf(a0, xB.z, bb1.x));
            float f03 = ex2f(fmaf(a0, xB.w, bb1.z));
            float f10 = ex2f(fmaf(a1, xB.x, bb0.y));
            float f11 = ex2f(fmaf(a1, xB.y, bb0.w));
            float f12 = ex2f(fmaf(a1, xB.z, bb1.y));
            float f13 = ex2f(fmaf(a1, xB.w, bb1.w));

            xsA0 = fmaf(e00, xA.x, fmaf(e01, xA.y, fmaf(e02, xA.z, fmaf(e03, xA.w, xsA0))));
            xsA1 = fmaf(e10, xA.x, fmaf(e11, xA.y, fmaf(e12, xA.z, fmaf(e13, xA.w, xsA1))));
            xsB0 = fmaf(f00, xB.x, fmaf(f01, xB.y, fmaf(f02, xB.z, fmaf(f03, xB.w, xsB0))));
            xsB1 = fmaf(f10, xB.x, fmaf(f11, xB.y, fmaf(f12, xB.z, fmaf(f13, xB.w, xsB1))));

            // ---- ctx accumulation: sub-pair 0 (s2 = S2) ----
            {
                unsigned long long pe00 = pack2(e00, e00), pe01 = pack2(e01, e01);
                unsigned long long pe10 = pack2(e10, e10), pe11 = pack2(e11, e11);
                unsigned long long pf00 = pack2(f00, f00), pf01 = pack2(f01, f01);
                unsigned long long pf10 = pack2(f10, f10), pf11 = pack2(f11, f11);
#pragma unroll
                for (int k = 0; k < 4; k++) {
                    float4 v4 = sm_vc[k * 512 + S2];
                    unsigned long long vlo = pack2(v4.x, v4.y);
                    unsigned long long vhi = pack2(v4.z, v4.w);
                    fma2(cA0[k], pe00, vlo); fma2(cA0[k], pe01, vhi);
                    fma2(cA1[k], pe10, vlo); fma2(cA1[k], pe11, vhi);
                    fma2(cB0[k], pf00, vlo); fma2(cB0[k], pf01, vhi);
                    fma2(cB1[k], pf10, vlo); fma2(cB1[k], pf11, vhi);
                }
            }
            // ---- ctx accumulation: sub-pair 1 (s2 = S2+1) ----
            {
                unsigned long long pe02 = pack2(e02, e02), pe03 = pack2(e03, e03);
                unsigned long long pe12 = pack2(e12, e12), pe13 = pack2(e13, e13);
                unsigned long long pf02 = pack2(f02, f02), pf03 = pack2(f03, f03);
                unsigned long long pf12 = pack2(f12, f12), pf13 = pack2(f13, f13);
#pragma unroll
                for (int k = 0; k < 4; k++) {
                    float4 v4 = sm_vc[k * 512 + S2 + 1];
                    unsigned long long vlo = pack2(v4.x, v4.y);
                    unsigned long long vhi = pack2(v4.z, v4.w);
                    fma2(cA0[k], pe02, vlo); fma2(cA0[k], pe03, vhi);
                    fma2(cA1[k], pe12, vlo); fma2(cA1[k], pe13, vhi);
                    fma2(cB0[k], pf02, vlo); fma2(cB0[k], pf03, vhi);
                    fma2(cB1[k], pf12, vlo); fma2(cB1[k], pf13, vhi);
                }
            }

            // ---- attn stores: one STG.128 per stream ----
            float4 r;
            r.x = e00 * izA0; r.y = e01 * izA0; r.z = e02 * izA0; r.w = e03 * izA0;
            __stcs(&pA0[i * 32], r);
            r.x = e10 * izA1; r.y = e11 * izA1; r.z = e12 * izA1; r.w = e13 * izA1;
            __stcs(&pA1[i * 32], r);
            r.x = f00 * izB0; r.y = f01 * izB0; r.z = f02 * izB0; r.w = f03 * izB0;
            __stcs(&pB0[i * 32], r);
            r.x = f10 * izB1; r.y = f11 * izB1; r.z = f12 * izB1; r.w = f13 * izB1;
            __stcs(&pB1[i * 32], r);
        }

        __syncthreads();   // race-free double buffering

        // ---- reductions (unchanged) ----
        znA0 = wsum(znA0); znA1 = wsum(znA1); znB0 = wsum(znB0); znB1 = wsum(znB1);
        xsA0 = wsum(xsA0); xsA1 = wsum(xsA1); xsB0 = wsum(xsB0); xsB1 = wsum(xsB1);
        float gA0[8], gA1[8], gB0[8], gB1[8];
#pragma unroll
        for (int k = 0; k < 4; k++) {
            unpack2(cA0[k], gA0[2 * k], gA0[2 * k + 1]);
            unpack2(cA1[k], gA1[2 * k], gA1[2 * k + 1]);
            unpack2(cB0[k], gB0[2 * k], gB0[2 * k + 1]);
            unpack2(cB1[k], gB1[2 * k], gB1[2 * k + 1]);
        }
#pragma unroll
        for (int j = 0; j < 8; j++) {
            gA0[j] = wsum(gA0[j]); gA1[j] = wsum(gA1[j]);
            gB0[j] = wsum(gB0[j]); gB1[j] = wsum(gB1[j]);
        }

        if (lane == 0) {
#pragma unroll
            for (int j = 0; j < 8; j++) {
                float vwj = g_vw[g][j];
                g_ctxs[b0][q0][h0 * 8 + j] = izA0 * fmaf(xsA0, vwj, gA0[j]);
                g_ctxs[b0][q1][h1 * 8 + j] = izA1 * fmaf(xsA1, vwj, gA1[j]);
                g_ctxs[b1][q0][h0 * 8 + j] = izB0 * fmaf(xsB0, vwj, gB0[j]);
                g_ctxs[b1][q1][h1 * 8 + j] = izB1 * fmaf(xsB1, vwj, gB1[j]);
            }
        }
        izA0 = 1.0f / znA0; izA1 = 1.0f / znA1;
        izB0 = 1.0f / znB0; izB1 = 1.0f / znB1;
        cur ^= 1;
    }

    // ================= PHASE 3: fused out-projection =================
    ticket_barrier(&g_done2, tid);

    float* sw = smem;   // o_w 64x64 = 16 KB (sm_vc region, now dead)
    ((float4*)sw)[tid] = ((const float4*)o_w)[tid];
    ((float4*)sw)[tid + 512] = ((const float4*)o_w)[tid + 512];
    __syncthreads();

    const int q = tid >> 6, e = tid & 63;
    const float bias = __ldg(&o_b[e]);
#pragma unroll
    for (int r = 0; r < 7; r++) {
        int b = cid + 148 * r;
        if (b < 1024) {
            const float4* cr = (const float4*)&g_ctxs[b][q][0];
            float acc = bias;
#pragma unroll
            for (int k = 0; k < 16; k++) {
                float4 c4 = __ldg(&cr[k]);
                acc = fmaf(c4.x, sw[(4 * k + 0) * 64 + e], acc);
                acc = fmaf(c4.y, sw[(4 * k + 1) * 64 + e], acc);
                acc = fmaf(c4.z, sw[(4 * k + 2) * 64 + e], acc);
                acc = fmaf(c4.w, sw[(4 * k + 3) * 64 + e], acc);
            }
            out[(size_t)b * 512 + tid] = acc;
        }
    }
}

// ---------------------------------------------------------------------------
extern "C" void kernel_launch(void* const* d_in, const int* in_sizes, int n_in,
                              void* d_out, int out_size) {
    const float* x       = (const float*)d_in[0];
    const float* queries = (const float*)d_in[1];
    const float* fe_w    = (const float*)d_in[2];
    const float* fe_b    = (const float*)d_in[3];
    const float* pos_emb = (const float*)d_in[4];
    const float* k_w     = (const float*)d_in[5];
    const float* k_b     = (const float*)d_in[6];
    const float* v_w     = (const float*)d_in[7];
    const float* v_b     = (const float*)d_in[8];
    const float* o_w     = (const float*)d_in[9];
    const float* o_b     = (const float*)d_in[10];

    float* out  = (float*)d_out;                 // [1024, 512]
    float* attn = out + 1024 * 512;              // [1024, 8, 8, 1024]

    int smem_bytes = 16384 * 4;                  // 65,536 B
    cudaFuncSetAttribute(k_fused, cudaFuncAttributeMaxDynamicSharedMemorySize, smem_bytes);

    k_fused<<<dim3(74, 2), 512, smem_bytes>>>(x, queries, fe_w, fe_b, pos_emb,
                                              k_w, k_b, v_w, v_b, o_w, o_b,
                                              out, attn);
}

// round 15
// speedup vs baseline: 1.2270x; 1.2270x over previous
#include <cuda_runtime.h>

// ---------------------------------------------------------------------------
// GroupedQueryAttention — fused persistent kernel, 256thr x 2 CTA/SM (R7-best).
//   x_embed affine in scalar x[b,s] => score(log2) = a[g,p]*x[b,s] + bconst[g,p,s]
//   attn = e/Z ; ctx = invZ*(sum_s e*vc[s,:] + (sum_s e*x)*vw) ; out = ctx@o_w+o_b
//
// Grid (74,4) = 296 CTAs = 2/SM (<= 304 capacity) -> all co-resident; ticket
// barriers (n=296) are deadlock-free and graph-replay-safe (monotonic ctr).
// 2 CTAs/SM is the measured-best main shape (R7, 81.98us): one CTA's
// barrier/reduction phases overlap the other's inner loop.
// Phase 1: table build, <=4 s-rows per CTA. Phase 2: R7 main body (g=y>>1,
// wp=8*(y&1)+w, pairs 2wp/2wp+1, NB=2 rows/chunk, fused next-chunk Z) + the
// R10 race-fix sync. Phase 3: out-projection, <=4 b-rows per CTA.
// ---------------------------------------------------------------------------

#define LOG2E_OVER_SCALE ((float)(1.4426950408889634 / 2.8284271247461903))

// g_b4[g][wp][s2][4] = { b(2s2,p0), b(2s2,p1), b(2s2+1,p0), b(2s2+1,p1) }
__device__ __align__(16) float g_b4[2][16][512][4];   // 256 KB
// g_vc4[g][jj][s2][4] = { vc(2s2,2jj), vc(2s2,2jj+1), vc(2s2+1,2jj), vc(2s2+1,2jj+1) }
__device__ __align__(16) float g_vc4[2][4][512][4];   // 64 KB
__device__ float g_a[2][32];
__device__ float g_vw[2][8];
__device__ __align__(16) float g_ctxs[1024][8][64];   // 2 MB staging
__device__ unsigned g_done1;
__device__ unsigned g_done2;

__device__ __forceinline__ float ex2f(float x) {
    float r; asm("ex2.approx.ftz.f32 %0, %1;" : "=f"(r) : "f"(x)); return r;
}
__device__ __forceinline__ unsigned long long pack2(float a, float b) {
    unsigned long long r; asm("mov.b64 %0, {%1, %2};" : "=l"(r) : "f"(a), "f"(b)); return r;
}
__device__ __forceinline__ void unpack2(unsigned long long v, float& a, float& b) {
    asm("mov.b64 {%0, %1}, %2;" : "=f"(a), "=f"(b) : "l"(v));
}
__device__ __forceinline__ void fma2(unsigned long long& d, unsigned long long a, unsigned long long b) {
    asm("fma.rn.f32x2 %0, %1, %2, %0;" : "+l"(d) : "l"(a), "l"(b));
}
__device__ __forceinline__ float wsum(float v) {
#pragma unroll
    for (int m = 16; m > 0; m >>= 1) v += __shfl_xor_sync(0xffffffffu, v, m);
    return v;
}
__device__ __forceinline__ void ticket_barrier(unsigned* ctr, int tid, unsigned n) {
    __threadfence();
    __syncthreads();
    if (tid == 0) {
        unsigned ticket = atomicAdd(ctr, 1u);
        unsigned target = ticket - (ticket % n) + n;
        while ((int)(atomicAdd(ctr, 0u) - target) < 0) __nanosleep(128);
    }
    __syncthreads();
    __threadfence();
}

__global__ __launch_bounds__(256, 2) void k_fused(
        const float* __restrict__ x,
        const float* __restrict__ queries,
        const float* __restrict__ fe_w,
        const float* __restrict__ fe_b,
        const float* __restrict__ pos_emb,
        const float* __restrict__ k_w,
        const float* __restrict__ k_b,
        const float* __restrict__ v_w,
        const float* __restrict__ v_b,
        const float* __restrict__ o_w,
        const float* __restrict__ o_b,
        float* __restrict__ out,
        float* __restrict__ attn_out) {
    extern __shared__ float smem[];
    // main-phase regions:
    float4* sm_vc = (float4*)smem;                  // [4][512] f4 = 32 KB
    float2* sm_x = (float2*)(smem + 8192);          // [2 buf][2 rows][512] f2 = 16 KB
    // phase-1 scratch (overlays sm_vc; dead after barrier 1):
    float* s_kw = smem;                             // [64][16] = 1024 f
    float* s_vw = smem + 1024;                      // 1024 f
    float* s_q = smem + 2048;                       // 512 f
    float* s_feb = smem + 2560;                     // 64 f
    float* s_red = smem + 2624;                     // [2][16][8] = 256 f
    float* s_kcrow = smem + 2880;                   // 16 f

    const int tid = threadIdx.x;
    const int cid = blockIdx.y * 74 + blockIdx.x;   // 0..295

    // ================= PHASE 1: distributed table build =================
    ((float4*)s_kw)[tid] = ((const float4*)k_w)[tid & 255];
    if (tid < 256) ((float4*)s_vw)[tid] = ((const float4*)v_w)[tid];
    if (tid < 128) ((float4*)s_q)[tid] = ((const float4*)queries)[tid];
    else if (tid < 144) ((float4*)s_feb)[tid - 128] = ((const float4*)fe_b)[tid - 128];
    __syncthreads();

    {
        const int j = tid & 15, d8 = (tid >> 4) & 7, kv = tid >> 7;  // 16*8*2=256
        for (int r = 0; r < 4; r++) {
            const int s = cid + 296 * r;
            const bool valid = (s < 1024);
            float part = 0.f;
            if (valid) {
                const float* pos = pos_emb + s * 64;
                const float* wcol = kv ? s_vw : s_kw;
#pragma unroll
                for (int u = 0; u < 8; u++) {
                    int d = d8 * 8 + u;
                    float e = s_feb[d] + __ldg(&pos[d]);
                    part = fmaf(e, wcol[d * 16 + j], part);
                }
            }
            s_red[(kv * 16 + j) * 8 + d8] = part;
            __syncthreads();
            if (tid < 32 && valid) {   // combine 8 d-partials
                int kv2 = tid >> 4, j2 = tid & 15;
                const float* pr = &s_red[(kv2 * 16 + j2) * 8];
                float v = pr[0] + pr[1] + pr[2] + pr[3] + pr[4] + pr[5] + pr[6] + pr[7];
                if (kv2 == 0) {
                    s_kcrow[j2] = __ldg(&k_b[j2]) + v;
                } else {
                    float vc = __ldg(&v_b[j2]) + v;
                    g_vc4[j2 >> 3][(j2 & 7) >> 1][s >> 1][(s & 1) * 2 + (j2 & 1)] = vc;
                }
            }
            __syncthreads();
            if (tid < 64 && valid) {   // bconst for this row
                int gg = tid >> 5, p = tid & 31, rb = p >> 3, q = p & 7, h = gg * 4 + rb;
                float acc = 0.f;
#pragma unroll
                for (int j3 = 0; j3 < 8; j3++)
                    acc = fmaf(s_q[q * 64 + h * 8 + j3], s_kcrow[gg * 8 + j3], acc);
                g_b4[gg][p >> 1][s >> 1][(s & 1) * 2 + (p & 1)] = acc * LOG2E_OVER_SCALE;
            }
            __syncthreads();
        }
    }
    if (cid == 0) {   // a[] and vw (once)
        if (tid < 32) {
            int j = tid & 15, kv = tid >> 4;
            const float* wcol = kv ? s_vw : s_kw;
            float pk = 0.f;
            for (int d = 0; d < 64; d++)
                pk = fmaf(__ldg(&fe_w[d]), wcol[d * 16 + j], pk);
            if (kv) g_vw[j >> 3][j & 7] = pk;
            else s_kcrow[j] = pk;   // reuse as kwf
        }
        __syncthreads();
        if (tid < 64) {
            int gg = tid >> 5, p = tid & 31, rb = p >> 3, q = p & 7, h = gg * 4 + rb;
            float sv = 0.f;
#pragma unroll
            for (int j = 0; j < 8; j++)
                sv = fmaf(s_q[q * 64 + h * 8 + j], s_kcrow[gg * 8 + j], sv);
            g_a[gg][p] = sv * LOG2E_OVER_SCALE;
        }
    }

    ticket_barrier(&g_done1, tid, 296u);

    // ================= PHASE 2: main (R7 measured-best body) =================
    const int w = tid >> 5, lane = tid & 31;
    const int g = blockIdx.y >> 1;
    const int wp = ((blockIdx.y & 1) << 3) + w;
    const int p0 = 2 * wp, p1 = p0 + 1;
    const float a0 = g_a[g][p0], a1 = g_a[g][p1];
    const int h0 = g * 4 + (p0 >> 3), q0 = p0 & 7;
    const int h1 = g * 4 + (p1 >> 3), q1 = p1 & 7;

    {
        const float4* vs = (const float4*)&g_vc4[g][0][0][0];
#pragma unroll
        for (int i = 0; i < 8; i++) sm_vc[tid + 256 * i] = vs[tid + 256 * i];
    }

    const int c0 = blockIdx.x;
    const float4* bptr = (const float4*)&g_b4[g][wp][0][0];

    // ---- prologue: x + Z for first chunk ----
    ((float4*)sm_x)[tid] = ((const float4*)(x + (size_t)(2 * c0) * 1024))[tid];
    ((float4*)sm_x)[tid + 256] = ((const float4*)(x + (size_t)(2 * c0) * 1024))[tid + 256];
    __syncthreads();
    float izA0, izA1, izB0, izB1;
    {
        float zA0 = 0.f, zA1 = 0.f, zB0 = 0.f, zB1 = 0.f;
#pragma unroll
        for (int i = 0; i < 16; i++) {
            int s2 = 32 * i + lane;
            float4 bb = bptr[s2];
            float2 xA = sm_x[s2];
            float2 xB = sm_x[512 + s2];
            zA0 += ex2f(fmaf(a0, xA.x, bb.x)) + ex2f(fmaf(a0, xA.y, bb.z));
            zA1 += ex2f(fmaf(a1, xA.x, bb.y)) + ex2f(fmaf(a1, xA.y, bb.w));
            zB0 += ex2f(fmaf(a0, xB.x, bb.x)) + ex2f(fmaf(a0, xB.y, bb.z));
            zB1 += ex2f(fmaf(a1, xB.x, bb.y)) + ex2f(fmaf(a1, xB.y, bb.w));
        }
        izA0 = 1.0f / wsum(zA0); izA1 = 1.0f / wsum(zA1);
        izB0 = 1.0f / wsum(zB0); izB1 = 1.0f / wsum(zB1);
    }

    int cur = 0;
    for (int c = c0; c < 512; c += 74) {
        const int b0 = 2 * c, b1 = b0 + 1;
        const int cn = c + 74;
        if (cn < 512) {
            ((float4*)&sm_x[(cur ^ 1) * 1024])[tid] =
                ((const float4*)(x + (size_t)(2 * cn) * 1024))[tid];
            ((float4*)&sm_x[(cur ^ 1) * 1024])[tid + 256] =
                ((const float4*)(x + (size_t)(2 * cn) * 1024))[tid + 256];
        }
        __syncthreads();

        const float2* xc = &sm_x[cur * 1024];
        const float2* xn = &sm_x[(cur ^ 1) * 1024];
        float2* oA0 = (float2*)(attn_out + (((size_t)b0 * 8 + h0) * 8 + q0) * 1024) + lane;
        float2* oA1 = (float2*)(attn_out + (((size_t)b0 * 8 + h1) * 8 + q1) * 1024) + lane;
        float2* oB0 = (float2*)(attn_out + (((size_t)b1 * 8 + h0) * 8 + q0) * 1024) + lane;
        float2* oB1 = (float2*)(attn_out + (((size_t)b1 * 8 + h1) * 8 + q1) * 1024) + lane;

        float znA0 = 0.f, znA1 = 0.f, znB0 = 0.f, znB1 = 0.f;
        float xsA0 = 0.f, xsA1 = 0.f, xsB0 = 0.f, xsB1 = 0.f;
        unsigned long long cA0[4], cA1[4], cB0[4], cB1[4];
#pragma unroll
        for (int k = 0; k < 4; k++) { cA0[k] = cA1[k] = cB0[k] = cB1[k] = 0ull; }

#pragma unroll
        for (int i = 0; i < 16; i++) {
            int s2 = 32 * i + lane;
            float4 bb = bptr[s2];
            float2 xA = xc[s2];
            float2 xB = xc[512 + s2];
            float2 nA = xn[s2];
            float2 nB = xn[512 + s2];

            // Z pipeline for next chunk (reuses bb)
            znA0 += ex2f(fmaf(a0, nA.x, bb.x)) + ex2f(fmaf(a0, nA.y, bb.z));
            znA1 += ex2f(fmaf(a1, nA.x, bb.y)) + ex2f(fmaf(a1, nA.y, bb.w));
            znB0 += ex2f(fmaf(a0, nB.x, bb.x)) + ex2f(fmaf(a0, nB.y, bb.z));
            znB1 += ex2f(fmaf(a1, nB.x, bb.y)) + ex2f(fmaf(a1, nB.y, bb.w));

            float e00 = ex2f(fmaf(a0, xA.x, bb.x));
            float e01 = ex2f(fmaf(a0, xA.y, bb.z));
            float e10 = ex2f(fmaf(a1, xA.x, bb.y));
            float e11 = ex2f(fmaf(a1, xA.y, bb.w));
            float f00 = ex2f(fmaf(a0, xB.x, bb.x));
            float f01 = ex2f(fmaf(a0, xB.y, bb.z));
            float f10 = ex2f(fmaf(a1, xB.x, bb.y));
            float f11 = ex2f(fmaf(a1, xB.y, bb.w));

            xsA0 = fmaf(e00, xA.x, fmaf(e01, xA.y, xsA0));
            xsA1 = fmaf(e10, xA.x, fmaf(e11, xA.y, xsA1));
            xsB0 = fmaf(f00, xB.x, fmaf(f01, xB.y, xsB0));
            xsB1 = fmaf(f10, xB.x, fmaf(f11, xB.y, xsB1));

            unsigned long long pe00 = pack2(e00, e00), pe01 = pack2(e01, e01);
            unsigned long long pe10 = pack2(e10, e10), pe11 = pack2(e11, e11);
            unsigned long long pf00 = pack2(f00, f00), pf01 = pack2(f01, f01);
            unsigned long long pf10 = pack2(f10, f10), pf11 = pack2(f11, f11);
#pragma unroll
            for (int k = 0; k < 4; k++) {
                float4 v4 = sm_vc[k * 512 + s2];
                unsigned long long vlo = pack2(v4.x, v4.y);
                unsigned long long vhi = pack2(v4.z, v4.w);
                fma2(cA0[k], pe00, vlo); fma2(cA0[k], pe01, vhi);
                fma2(cA1[k], pe10, vlo); fma2(cA1[k], pe11, vhi);
                fma2(cB0[k], pf00, vlo); fma2(cB0[k], pf01, vhi);
                fma2(cB1[k], pf10, vlo); fma2(cB1[k], pf11, vhi);
            }

            float2 r;
            r.x = e00 * izA0; r.y = e01 * izA0; __stcs(&oA0[i * 32], r);
            r.x = e10 * izA1; r.y = e11 * izA1; __stcs(&oA1[i * 32], r);
            r.x = f00 * izB0; r.y = f01 * izB0; __stcs(&oB0[i * 32], r);
            r.x = f10 * izB1; r.y = f11 * izB1; __stcs(&oB1[i * 32], r);
        }

        // RACE FIX: separate this chunk's sm_x reads from the next chunk's
        // store into the aliased buffer.
        __syncthreads();

        // reductions
        znA0 = wsum(znA0); znA1 = wsum(znA1); znB0 = wsum(znB0); znB1 = wsum(znB1);
        xsA0 = wsum(xsA0); xsA1 = wsum(xsA1); xsB0 = wsum(xsB0); xsB1 = wsum(xsB1);
        float gA0[8], gA1[8], gB0[8], gB1[8];
#pragma unroll
        for (int k = 0; k < 4; k++) {
            unpack2(cA0[k], gA0[2 * k], gA0[2 * k + 1]);
            unpack2(cA1[k], gA1[2 * k], gA1[2 * k + 1]);
            unpack2(cB0[k], gB0[2 * k], gB0[2 * k + 1]);
            unpack2(cB1[k], gB1[2 * k], gB1[2 * k + 1]);
        }
#pragma unroll
        for (int j = 0; j < 8; j++) {
            gA0[j] = wsum(gA0[j]); gA1[j] = wsum(gA1[j]);
            gB0[j] = wsum(gB0[j]); gB1[j] = wsum(gB1[j]);
        }

        if (lane == 0) {
#pragma unroll
            for (int j = 0; j < 8; j++) {
                float vwj = g_vw[g][j];
                g_ctxs[b0][q0][h0 * 8 + j] = izA0 * fmaf(xsA0, vwj, gA0[j]);
                g_ctxs[b0][q1][h1 * 8 + j] = izA1 * fmaf(xsA1, vwj, gA1[j]);
                g_ctxs[b1][q0][h0 * 8 + j] = izB0 * fmaf(xsB0, vwj, gB0[j]);
                g_ctxs[b1][q1][h1 * 8 + j] = izB1 * fmaf(xsB1, vwj, gB1[j]);
            }
        }
        izA0 = 1.0f / znA0; izA1 = 1.0f / znA1;
        izB0 = 1.0f / znB0; izB1 = 1.0f / znB1;
        cur ^= 1;
    }

    // ================= PHASE 3: distributed out-projection =================
    ticket_barrier(&g_done2, tid, 296u);

    float* sw = smem;   // o_w 64x64 = 16 KB (sm_vc region, now dead)
#pragma unroll
    for (int i = 0; i < 4; i++)
        ((float4*)sw)[tid + 256 * i] = ((const float4*)o_w)[tid + 256 * i];
    __syncthreads();

#pragma unroll
    for (int r = 0; r < 4; r++) {
        int b = cid + 296 * r;
        if (b < 1024) {
#pragma unroll
            for (int half = 0; half < 2; half++) {
                int idx = tid + 256 * half;
                int q = idx >> 6, e = idx & 63;
                const float4* cr = (const float4*)&g_ctxs[b][q][0];
                float acc = __ldg(&o_b[e]);
#pragma unroll
                for (int k = 0; k < 16; k++) {
                    float4 c4 = __ldg(&cr[k]);
                    acc = fmaf(c4.x, sw[(4 * k + 0) * 64 + e], acc);
                    acc = fmaf(c4.y, sw[(4 * k + 1) * 64 + e], acc);
                    acc = fmaf(c4.z, sw[(4 * k + 2) * 64 + e], acc);
                    acc = fmaf(c4.w, sw[(4 * k + 3) * 64 + e], acc);
                }
                out[(size_t)b * 512 + idx] = acc;
            }
        }
    }
}

// ---------------------------------------------------------------------------
extern "C" void kernel_launch(void* const* d_in, const int* in_sizes, int n_in,
                              void* d_out, int out_size) {
    const float* x       = (const float*)d_in[0];
    const float* queries = (const float*)d_in[1];
    const float* fe_w    = (const float*)d_in[2];
    const float* fe_b    = (const float*)d_in[3];
    const float* pos_emb = (const float*)d_in[4];
    const float* k_w     = (const float*)d_in[5];
    const float* k_b     = (const float*)d_in[6];
    const float* v_w     = (const float*)d_in[7];
    const float* v_b     = (const float*)d_in[8];
    const float* o_w     = (const float*)d_in[9];
    const float* o_b     = (const float*)d_in[10];

    float* out  = (float*)d_out;                 // [1024, 512]
    float* attn = out + 1024 * 512;              // [1024, 8, 8, 1024]

    int smem_bytes = (8192 + 4096) * 4;          // 49,152 B per CTA (2/SM = 96 KB)
    cudaFuncSetAttribute(k_fused, cudaFuncAttributeMaxDynamicSharedMemorySize, smem_bytes);

    k_fused<<<dim3(74, 4), 256, smem_bytes>>>(x, queries, fe_w, fe_b, pos_emb,
                                              k_w, k_b, v_w, v_b, o_w, o_b,
                                              out, attn);
}

// round 16
// speedup vs baseline: 1.2417x; 1.0120x over previous
#include <cuda_runtime.h>

// ---------------------------------------------------------------------------
// GroupedQueryAttention — fused persistent kernel, 256thr x 2 CTA/SM (R15 base).
//   x_embed affine in scalar x[b,s] => score(log2) = a[g,p]*x[b,s] + bconst[g,p,s]
//   attn = e/Z ; ctx = invZ*(sum_s e*vc[s,:] + (sum_s e*x)*vw) ; out = ctx@o_w+o_b
//
// Grid (74,4) = 296 CTAs = 2/SM -> co-resident; ticket barriers (n=296) safe.
// R16 deltas vs R15 (both micro, register-neutral):
//  - sm_x stores the two batch rows INTERLEAVED ({A0,A1,B0,B1} per s2 float4):
//    inner loop x reads are 2 LDS.128 instead of 4 LDS.64 (same bytes).
//  - Z-pipeline (16 EX2/iter) skipped on each CTA's final chunk (cn>=512).
// ---------------------------------------------------------------------------

#define LOG2E_OVER_SCALE ((float)(1.4426950408889634 / 2.8284271247461903))

// g_b4[g][wp][s2][4] = { b(2s2,p0), b(2s2,p1), b(2s2+1,p0), b(2s2+1,p1) }
__device__ __align__(16) float g_b4[2][16][512][4];   // 256 KB
// g_vc4[g][jj][s2][4] = { vc(2s2,2jj), vc(2s2,2jj+1), vc(2s2+1,2jj), vc(2s2+1,2jj+1) }
__device__ __align__(16) float g_vc4[2][4][512][4];   // 64 KB
__device__ float g_a[2][32];
__device__ float g_vw[2][8];
__device__ __align__(16) float g_ctxs[1024][8][64];   // 2 MB staging
__device__ unsigned g_done1;
__device__ unsigned g_done2;

__device__ __forceinline__ float ex2f(float x) {
    float r; asm("ex2.approx.ftz.f32 %0, %1;" : "=f"(r) : "f"(x)); return r;
}
__device__ __forceinline__ unsigned long long pack2(float a, float b) {
    unsigned long long r; asm("mov.b64 %0, {%1, %2};" : "=l"(r) : "f"(a), "f"(b)); return r;
}
__device__ __forceinline__ void unpack2(unsigned long long v, float& a, float& b) {
    asm("mov.b64 {%0, %1}, %2;" : "=f"(a), "=f"(b) : "l"(v));
}
__device__ __forceinline__ void fma2(unsigned long long& d, unsigned long long a, unsigned long long b) {
    asm("fma.rn.f32x2 %0, %1, %2, %0;" : "+l"(d) : "l"(a), "l"(b));
}
__device__ __forceinline__ float wsum(float v) {
#pragma unroll
    for (int m = 16; m > 0; m >>= 1) v += __shfl_xor_sync(0xffffffffu, v, m);
    return v;
}
__device__ __forceinline__ void ticket_barrier(unsigned* ctr, int tid, unsigned n) {
    __threadfence();
    __syncthreads();
    if (tid == 0) {
        unsigned ticket = atomicAdd(ctr, 1u);
        unsigned target = ticket - (ticket % n) + n;
        while ((int)(atomicAdd(ctr, 0u) - target) < 0) __nanosleep(128);
    }
    __syncthreads();
    __threadfence();
}

__global__ __launch_bounds__(256, 2) void k_fused(
        const float* __restrict__ x,
        const float* __restrict__ queries,
        const float* __restrict__ fe_w,
        const float* __restrict__ fe_b,
        const float* __restrict__ pos_emb,
        const float* __restrict__ k_w,
        const float* __restrict__ k_b,
        const float* __restrict__ v_w,
        const float* __restrict__ v_b,
        const float* __restrict__ o_w,
        const float* __restrict__ o_b,
        float* __restrict__ out,
        float* __restrict__ attn_out) {
    extern __shared__ float smem[];
    // main-phase regions:
    float4* sm_vc = (float4*)smem;                  // [4][512] f4 = 32 KB
    float4* sm_x4 = (float4*)(smem + 8192);         // [2 buf][512 s2] f4 = 16 KB
    // phase-1 scratch (overlays sm_vc; dead after barrier 1):
    float* s_kw = smem;                             // [64][16] = 1024 f
    float* s_vw = smem + 1024;                      // 1024 f
    float* s_q = smem + 2048;                       // 512 f
    float* s_feb = smem + 2560;                     // 64 f
    float* s_red = smem + 2624;                     // [2][16][8] = 256 f
    float* s_kcrow = smem + 2880;                   // 16 f

    const int tid = threadIdx.x;
    const int cid = blockIdx.y * 74 + blockIdx.x;   // 0..295

    // ================= PHASE 1: distributed table build =================
    ((float4*)s_kw)[tid] = ((const float4*)k_w)[tid & 255];
    if (tid < 256) ((float4*)s_vw)[tid] = ((const float4*)v_w)[tid];
    if (tid < 128) ((float4*)s_q)[tid] = ((const float4*)queries)[tid];
    else if (tid < 144) ((float4*)s_feb)[tid - 128] = ((const float4*)fe_b)[tid - 128];
    __syncthreads();

    {
        const int j = tid & 15, d8 = (tid >> 4) & 7, kv = tid >> 7;  // 16*8*2=256
        for (int r = 0; r < 4; r++) {
            const int s = cid + 296 * r;
            const bool valid = (s < 1024);
            float part = 0.f;
            if (valid) {
                const float* pos = pos_emb + s * 64;
                const float* wcol = kv ? s_vw : s_kw;
#pragma unroll
                for (int u = 0; u < 8; u++) {
                    int d = d8 * 8 + u;
                    float e = s_feb[d] + __ldg(&pos[d]);
                    part = fmaf(e, wcol[d * 16 + j], part);
                }
            }
            s_red[(kv * 16 + j) * 8 + d8] = part;
            __syncthreads();
            if (tid < 32 && valid) {   // combine 8 d-partials
                int kv2 = tid >> 4, j2 = tid & 15;
                const float* pr = &s_red[(kv2 * 16 + j2) * 8];
                float v = pr[0] + pr[1] + pr[2] + pr[3] + pr[4] + pr[5] + pr[6] + pr[7];
                if (kv2 == 0) {
                    s_kcrow[j2] = __ldg(&k_b[j2]) + v;
                } else {
                    float vc = __ldg(&v_b[j2]) + v;
                    g_vc4[j2 >> 3][(j2 & 7) >> 1][s >> 1][(s & 1) * 2 + (j2 & 1)] = vc;
                }
            }
            __syncthreads();
            if (tid < 64 && valid) {   // bconst for this row
                int gg = tid >> 5, p = tid & 31, rb = p >> 3, q = p & 7, h = gg * 4 + rb;
                float acc = 0.f;
#pragma unroll
                for (int j3 = 0; j3 < 8; j3++)
                    acc = fmaf(s_q[q * 64 + h * 8 + j3], s_kcrow[gg * 8 + j3], acc);
                g_b4[gg][p >> 1][s >> 1][(s & 1) * 2 + (p & 1)] = acc * LOG2E_OVER_SCALE;
            }
            __syncthreads();
        }
    }
    if (cid == 0) {   // a[] and vw (once)
        if (tid < 32) {
            int j = tid & 15, kv = tid >> 4;
            const float* wcol = kv ? s_vw : s_kw;
            float pk = 0.f;
            for (int d = 0; d < 64; d++)
                pk = fmaf(__ldg(&fe_w[d]), wcol[d * 16 + j], pk);
            if (kv) g_vw[j >> 3][j & 7] = pk;
            else s_kcrow[j] = pk;   // reuse as kwf
        }
        __syncthreads();
        if (tid < 64) {
            int gg = tid >> 5, p = tid & 31, rb = p >> 3, q = p & 7, h = gg * 4 + rb;
            float sv = 0.f;
#pragma unroll
            for (int j = 0; j < 8; j++)
                sv = fmaf(s_q[q * 64 + h * 8 + j], s_kcrow[gg * 8 + j], sv);
            g_a[gg][p] = sv * LOG2E_OVER_SCALE;
        }
    }

    ticket_barrier(&g_done1, tid, 296u);

    // ================= PHASE 2: main (R15 body, interleaved x) ==============
    const int w = tid >> 5, lane = tid & 31;
    const int g = blockIdx.y >> 1;
    const int wp = ((blockIdx.y & 1) << 3) + w;
    const int p0 = 2 * wp, p1 = p0 + 1;
    const float a0 = g_a[g][p0], a1 = g_a[g][p1];
    const int h0 = g * 4 + (p0 >> 3), q0 = p0 & 7;
    const int h1 = g * 4 + (p1 >> 3), q1 = p1 & 7;

    {
        const float4* vs = (const float4*)&g_vc4[g][0][0][0];
#pragma unroll
        for (int i = 0; i < 8; i++) sm_vc[tid + 256 * i] = vs[tid + 256 * i];
    }

    const int c0 = blockIdx.x;
    const float4* bptr = (const float4*)&g_b4[g][wp][0][0];

    // interleaved x staging: dst[s2] = {A[2s2],A[2s2+1],B[2s2],B[2s2+1]}
    auto stage_x = [&](int chunk, int buf) {
        const float2* ra = (const float2*)(x + (size_t)(2 * chunk) * 1024);
        const float2* rb = ra + 512;
        float4* dst = sm_x4 + buf * 512;
        float2 a0v = ra[tid], b0v = rb[tid];
        float2 a1v = ra[tid + 256], b1v = rb[tid + 256];
        dst[tid] = make_float4(a0v.x, a0v.y, b0v.x, b0v.y);
        dst[tid + 256] = make_float4(a1v.x, a1v.y, b1v.x, b1v.y);
    };

    // ---- prologue: x + Z for first chunk ----
    stage_x(c0, 0);
    __syncthreads();
    float izA0, izA1, izB0, izB1;
    {
        float zA0 = 0.f, zA1 = 0.f, zB0 = 0.f, zB1 = 0.f;
#pragma unroll
        for (int i = 0; i < 16; i++) {
            int s2 = 32 * i + lane;
            float4 bb = bptr[s2];
            float4 xv = sm_x4[s2];
            zA0 += ex2f(fmaf(a0, xv.x, bb.x)) + ex2f(fmaf(a0, xv.y, bb.z));
            zA1 += ex2f(fmaf(a1, xv.x, bb.y)) + ex2f(fmaf(a1, xv.y, bb.w));
            zB0 += ex2f(fmaf(a0, xv.z, bb.x)) + ex2f(fmaf(a0, xv.w, bb.z));
            zB1 += ex2f(fmaf(a1, xv.z, bb.y)) + ex2f(fmaf(a1, xv.w, bb.w));
        }
        izA0 = 1.0f / wsum(zA0); izA1 = 1.0f / wsum(zA1);
        izB0 = 1.0f / wsum(zB0); izB1 = 1.0f / wsum(zB1);
    }

    int cur = 0;
    for (int c = c0; c < 512; c += 74) {
        const int b0 = 2 * c, b1 = b0 + 1;
        const int cn = c + 74;
        const bool last = (cn >= 512);
        if (!last) stage_x(cn, cur ^ 1);
        __syncthreads();

        const float4* xc4 = sm_x4 + cur * 512;
        const float4* xn4 = sm_x4 + (cur ^ 1) * 512;
        float2* oA0 = (float2*)(attn_out + (((size_t)b0 * 8 + h0) * 8 + q0) * 1024) + lane;
        float2* oA1 = (float2*)(attn_out + (((size_t)b0 * 8 + h1) * 8 + q1) * 1024) + lane;
        float2* oB0 = (float2*)(attn_out + (((size_t)b1 * 8 + h0) * 8 + q0) * 1024) + lane;
        float2* oB1 = (float2*)(attn_out + (((size_t)b1 * 8 + h1) * 8 + q1) * 1024) + lane;

        float znA0 = 0.f, znA1 = 0.f, znB0 = 0.f, znB1 = 0.f;
        float xsA0 = 0.f, xsA1 = 0.f, xsB0 = 0.f, xsB1 = 0.f;
        unsigned long long cA0[4], cA1[4], cB0[4], cB1[4];
#pragma unroll
        for (int k = 0; k < 4; k++) { cA0[k] = cA1[k] = cB0[k] = cB1[k] = 0ull; }

#pragma unroll
        for (int i = 0; i < 16; i++) {
            int s2 = 32 * i + lane;
            float4 bb = bptr[s2];
            float4 xv = xc4[s2];

            // Z pipeline for next chunk (skipped on the final chunk)
            if (!last) {
                float4 nv = xn4[s2];
                znA0 += ex2f(fmaf(a0, nv.x, bb.x)) + ex2f(fmaf(a0, nv.y, bb.z));
                znA1 += ex2f(fmaf(a1, nv.x, bb.y)) + ex2f(fmaf(a1, nv.y, bb.w));
                znB0 += ex2f(fmaf(a0, nv.z, bb.x)) + ex2f(fmaf(a0, nv.w, bb.z));
                znB1 += ex2f(fmaf(a1, nv.z, bb.y)) + ex2f(fmaf(a1, nv.w, bb.w));
            }

            float e00 = ex2f(fmaf(a0, xv.x, bb.x));
            float e01 = ex2f(fmaf(a0, xv.y, bb.z));
            float e10 = ex2f(fmaf(a1, xv.x, bb.y));
            float e11 = ex2f(fmaf(a1, xv.y, bb.w));
            float f00 = ex2f(fmaf(a0, xv.z, bb.x));
            float f01 = ex2f(fmaf(a0, xv.w, bb.z));
            float f10 = ex2f(fmaf(a1, xv.z, bb.y));
            float f11 = ex2f(fmaf(a1, xv.w, bb.w));

            xsA0 = fmaf(e00, xv.x, fmaf(e01, xv.y, xsA0));
            xsA1 = fmaf(e10, xv.x, fmaf(e11, xv.y, xsA1));
            xsB0 = fmaf(f00, xv.z, fmaf(f01, xv.w, xsB0));
            xsB1 = fmaf(f10, xv.z, fmaf(f11, xv.w, xsB1));

            unsigned long long pe00 = pack2(e00, e00), pe01 = pack2(e01, e01);
            unsigned long long pe10 = pack2(e10, e10), pe11 = pack2(e11, e11);
            unsigned long long pf00 = pack2(f00, f00), pf01 = pack2(f01, f01);
            unsigned long long pf10 = pack2(f10, f10), pf11 = pack2(f11, f11);
#pragma unroll
            for (int k = 0; k < 4; k++) {
                float4 v4 = sm_vc[k * 512 + s2];
                unsigned long long vlo = pack2(v4.x, v4.y);
                unsigned long long vhi = pack2(v4.z, v4.w);
                fma2(cA0[k], pe00, vlo); fma2(cA0[k], pe01, vhi);
                fma2(cA1[k], pe10, vlo); fma2(cA1[k], pe11, vhi);
                fma2(cB0[k], pf00, vlo); fma2(cB0[k], pf01, vhi);
                fma2(cB1[k], pf10, vlo); fma2(cB1[k], pf11, vhi);
            }

            float2 r;
            r.x = e00 * izA0; r.y = e01 * izA0; __stcs(&oA0[i * 32], r);
            r.x = e10 * izA1; r.y = e11 * izA1; __stcs(&oA1[i * 32], r);
            r.x = f00 * izB0; r.y = f01 * izB0; __stcs(&oB0[i * 32], r);
            r.x = f10 * izB1; r.y = f11 * izB1; __stcs(&oB1[i * 32], r);
        }

        // RACE FIX: separate this chunk's sm_x reads from the next chunk's
        // store into the aliased buffer.
        __syncthreads();

        // reductions
        znA0 = wsum(znA0); znA1 = wsum(znA1); znB0 = wsum(znB0); znB1 = wsum(znB1);
        xsA0 = wsum(xsA0); xsA1 = wsum(xsA1); xsB0 = wsum(xsB0); xsB1 = wsum(xsB1);
        float gA0[8], gA1[8], gB0[8], gB1[8];
#pragma unroll
        for (int k = 0; k < 4; k++) {
            unpack2(cA0[k], gA0[2 * k], gA0[2 * k + 1]);
            unpack2(cA1[k], gA1[2 * k], gA1[2 * k + 1]);
            unpack2(cB0[k], gB0[2 * k], gB0[2 * k + 1]);
            unpack2(cB1[k], gB1[2 * k], gB1[2 * k + 1]);
        }
#pragma unroll
        for (int j = 0; j < 8; j++) {
            gA0[j] = wsum(gA0[j]); gA1[j] = wsum(gA1[j]);
            gB0[j] = wsum(gB0[j]); gB1[j] = wsum(gB1[j]);
        }

        if (lane == 0) {
#pragma unroll
            for (int j = 0; j < 8; j++) {
                float vwj = g_vw[g][j];
                g_ctxs[b0][q0][h0 * 8 + j] = izA0 * fmaf(xsA0, vwj, gA0[j]);
                g_ctxs[b0][q1][h1 * 8 + j] = izA1 * fmaf(xsA1, vwj, gA1[j]);
                g_ctxs[b1][q0][h0 * 8 + j] = izB0 * fmaf(xsB0, vwj, gB0[j]);
                g_ctxs[b1][q1][h1 * 8 + j] = izB1 * fmaf(xsB1, vwj, gB1[j]);
            }
        }
        izA0 = 1.0f / znA0; izA1 = 1.0f / znA1;
        izB0 = 1.0f / znB0; izB1 = 1.0f / znB1;
        cur ^= 1;
    }

    // ================= PHASE 3: distributed out-projection =================
    ticket_barrier(&g_done2, tid, 296u);

    float* sw = smem;   // o_w 64x64 = 16 KB (sm_vc region, now dead)
#pragma unroll
    for (int i = 0; i < 4; i++)
        ((float4*)sw)[tid + 256 * i] = ((const float4*)o_w)[tid + 256 * i];
    __syncthreads();

#pragma unroll
    for (int r = 0; r < 4; r++) {
        int b = cid + 296 * r;
        if (b < 1024) {
#pragma unroll
            for (int half = 0; half < 2; half++) {
                int idx = tid + 256 * half;
                int q = idx >> 6, e = idx & 63;
                const float4* cr = (const float4*)&g_ctxs[b][q][0];
                float acc = __ldg(&o_b[e]);
#pragma unroll
                for (int k = 0; k < 16; k++) {
                    float4 c4 = __ldg(&cr[k]);
                    acc = fmaf(c4.x, sw[(4 * k + 0) * 64 + e], acc);
                    acc = fmaf(c4.y, sw[(4 * k + 1) * 64 + e], acc);
                    acc = fmaf(c4.z, sw[(4 * k + 2) * 64 + e], acc);
                    acc = fmaf(c4.w, sw[(4 * k + 3) * 64 + e], acc);
                }
                out[(size_t)b * 512 + idx] = acc;
            }
        }
    }
}

// ---------------------------------------------------------------------------
extern "C" void kernel_launch(void* const* d_in, const int* in_sizes, int n_in,
                              void* d_out, int out_size) {
    const float* x       = (const float*)d_in[0];
    const float* queries = (const float*)d_in[1];
    const float* fe_w    = (const float*)d_in[2];
    const float* fe_b    = (const float*)d_in[3];
    const float* pos_emb = (const float*)d_in[4];
    const float* k_w     = (const float*)d_in[5];
    const float* k_b     = (const float*)d_in[6];
    const float* v_w     = (const float*)d_in[7];
    const float* v_b     = (const float*)d_in[8];
    const float* o_w     = (const float*)d_in[9];
    const float* o_b     = (const float*)d_in[10];

    float* out  = (float*)d_out;                 // [1024, 512]
    float* attn = out + 1024 * 512;              // [1024, 8, 8, 1024]

    int smem_bytes = (8192 + 4096) * 4;          // 49,152 B per CTA (2/SM = 96 KB)
    cudaFuncSetAttribute(k_fused, cudaFuncAttributeMaxDynamicSharedMemorySize, smem_bytes);

    k_fused<<<dim3(74, 4), 256, smem_bytes>>>(x, queries, fe_w, fe_b, pos_emb,
                                              k_w, k_b, v_w, v_b, o_w, o_b,
                                              out, attn);
}